// round 8
// baseline (speedup 1.0000x reference)
#include <cuda_runtime.h>
#include <cstdint>

// Problem constants
#define N_CLS 64
#define K_SHOT 64
#define D_DIM 640
#define Q_PER 2048
#define NQ (N_CLS * Q_PER)        // 131072 query rows
#define SUP_ROWS (N_CLS * K_SHOT) // 4096 support rows

typedef unsigned long long ull;

// Staging buffers
__device__ __align__(16) float g_pu2[2][N_CLS * D_DIM]; // partial sums (k-halves)
__device__ __align__(16) float g_dis[N_CLS * K_SHOT];   // softmax numerators

// Prototypes pre-packed as fp16x2 in mma.m16n8k16 B-fragment order:
//   g_Ph[((s*8 + j)*32 + l)*2 + r] = {f16(P[n][k_e0]), f16(P[n][k_e1])},
//   k = 16s + 2t + e + 8r (t = l&3), n = 8j + (l>>2),  s = 0..39.
__device__ __align__(16) uint32_t g_Ph[40 * 8 * 32 * 2];   // 80 KB

// ---------------- helpers ----------------
__device__ __forceinline__ uint32_t f16x2_from(float lo, float hi) {
    uint32_t r;
    asm("cvt.rn.f16x2.f32 %0, %1, %2;" : "=r"(r) : "f"(hi), "f"(lo));
    return r;
}
__device__ __forceinline__ void cp16(uint32_t dst, const void* src) {
    asm volatile("cp.async.cg.shared.global [%0], [%1], 16;" :: "r"(dst), "l"(src));
}
#define CP_COMMIT() asm volatile("cp.async.commit_group;" ::: "memory")
#define CP_WAIT(n)  asm volatile("cp.async.wait_group %0;" :: "n"(n) : "memory")

__device__ __forceinline__ void mma_f16(float* d, const uint32_t* a, uint32_t b0, uint32_t b1) {
    asm volatile(
        "mma.sync.aligned.m16n8k16.row.col.f32.f16.f16.f32 "
        "{%0,%1,%2,%3}, {%4,%5,%6,%7}, {%8,%9}, {%0,%1,%2,%3};"
        : "+f"(d[0]), "+f"(d[1]), "+f"(d[2]), "+f"(d[3])
        : "r"(a[0]), "r"(a[1]), "r"(a[2]), "r"(a[3]), "r"(b0), "r"(b1));
}

// ======================================================================
// Kernel 1a: proto_unnorm partial sums, K split in halves.
// grid (10, 64): bx%5 = d-chunk, bx/5 = k-half. 640 CTAs.
// ======================================================================
__global__ void __launch_bounds__(128) proto_mean(const float* __restrict__ emb) {
    const int i  = blockIdx.y;
    const int h  = blockIdx.x / 5;
    const int d  = (blockIdx.x % 5) * 128 + threadIdx.x;
    const float* base = emb + (size_t)(h * 32 * N_CLS + i) * D_DIM + d;
    float s = 0.f;
    #pragma unroll 32
    for (int k = 0; k < 32; ++k)
        s += base[(size_t)k * (N_CLS * D_DIM)];
    g_pu2[h][i * D_DIM + d] = s;
}

// ======================================================================
// Kernel 1b: cosine-softmax numerators. grid (8, 64); warp = support row.
// Sums the two k-half partials into the mean.
// ======================================================================
__global__ void __launch_bounds__(256) proto_w(const float* __restrict__ emb) {
    const int i    = blockIdx.y;
    const int tid  = threadIdx.x;
    const int lane = tid & 31;
    const int wid  = tid >> 5;
    const int j    = blockIdx.x * 8 + wid;

    __shared__ float s_pu[D_DIM];
    __shared__ float s_red[8];
    __shared__ float s_pn;

    float pn2 = 0.f;
    for (int d = tid; d < D_DIM; d += 256) {
        float s = (g_pu2[0][i * D_DIM + d] + g_pu2[1][i * D_DIM + d]) * (1.0f / 64.0f);
        s_pu[d] = s;
        pn2 += s * s;
    }
    #pragma unroll
    for (int o = 16; o; o >>= 1) pn2 += __shfl_xor_sync(0xffffffffu, pn2, o);
    if (lane == 0) s_red[wid] = pn2;
    __syncthreads();
    if (tid == 0) {
        float t = 0.f;
        #pragma unroll
        for (int w = 0; w < 8; ++w) t += s_red[w];
        s_pn = fmaxf(sqrtf(t), 1e-8f);
    }
    __syncthreads();
    const float p_norm = s_pn;

    const float* row = emb + ((size_t)i * 64 + j) * D_DIM;
    float dot = 0.f, s2 = 0.f;
    #pragma unroll 5
    for (int d = lane; d < D_DIM; d += 32) {
        float a = row[d];
        dot += a * s_pu[d];
        s2  += a * a;
    }
    #pragma unroll
    for (int o = 16; o; o >>= 1) {
        dot += __shfl_xor_sync(0xffffffffu, dot, o);
        s2  += __shfl_xor_sync(0xffffffffu, s2, o);
    }
    if (lane == 0) {
        float sn = fmaxf(sqrtf(s2), 1e-8f);
        g_dis[i * 64 + j] = expf(dot / (p_norm * sn));
    }
}

// ======================================================================
// Kernel 1c: weighted prototype + norm + fp16 fragment scatter.
// grid (64), 640 threads (thread = dimension d). Support is L2-hot.
// ======================================================================
__global__ void __launch_bounds__(640) proto_pd(const float* __restrict__ emb) {
    const int i    = blockIdx.x;
    const int tid  = threadIdx.x;   // = d
    const int lane = tid & 31;
    const int wid  = tid >> 5;      // 0..19

    __shared__ float s_dis[64];
    __shared__ float s_p[D_DIM];
    __shared__ float s_red[20];
    __shared__ float s_isum, s_inorm;

    if (tid < 64) s_dis[tid] = g_dis[i * 64 + tid];
    __syncthreads();
    if (tid < 32) {
        float v = s_dis[tid] + s_dis[tid + 32];
        #pragma unroll
        for (int o = 16; o; o >>= 1) v += __shfl_xor_sync(0xffffffffu, v, o);
        if (tid == 0) s_isum = 1.0f / v;
    }
    __syncthreads();
    const float inv_sum = s_isum;

    const float* blk = emb + (size_t)i * 64 * D_DIM + tid;
    float pd = 0.f;
    #pragma unroll 8
    for (int j = 0; j < 64; ++j)
        pd += (s_dis[j] * inv_sum) * blk[(size_t)j * D_DIM];

    float q2 = pd * pd;
    #pragma unroll
    for (int o = 16; o; o >>= 1) q2 += __shfl_xor_sync(0xffffffffu, q2, o);
    if (lane == 0) s_red[wid] = q2;
    __syncthreads();
    if (tid == 0) {
        float t = 0.f;
        #pragma unroll
        for (int w = 0; w < 20; ++w) t += s_red[w];
        s_inorm = 1.0f / fmaxf(sqrtf(t), 1e-12f);
    }
    __syncthreads();
    s_p[tid] = pd * s_inorm;
    __syncthreads();

    // pack pairs into fp16 B-fragment layout
    if (tid < 320) {
        const int s  = tid >> 3;
        const int t4 = (tid & 7) >> 1;
        const int r  = tid & 1;
        const int k0 = 16 * s + 2 * t4 + 8 * r;
        const int ln = 4 * (i & 7) + t4;
        const int idx = ((s * 8 + (i >> 3)) * 32 + ln) * 2 + r;
        g_Ph[idx] = f16x2_from(s_p[k0], s_p[k0 + 1]);
    }
}

// ======================================================================
// Kernel 2: logits = query @ P^T * 10 via mma.sync m16n8k16 fp16.
//   M-tile 64, grid 2048 (6.92 waves -> 98.8% scheduling efficiency).
//   Block 256 thr: warp w = (m16 tile w&3) x (n32 half w>>2).
//   KT=64 (4 k16-steps), depth-3 cp.async ring (26.6KB/stage, 80KB).
//   A smem fp32 [64][72]; B smem 8KB/tile pre-packed fp16 fragments.
// ======================================================================
#define KT 64
#define NT (D_DIM / KT)                 // 10 K-tiles
#define A_PITCH 72
#define A_BYTES (64 * A_PITCH * 4)      // 18432
#define B_BYTES (4 * 8 * 32 * 2 * 4)    // 8192 (4 k16-steps)
#define STAGE_BYTES (A_BYTES + B_BYTES) // 26624
#define SMEM_TOTAL (3 * STAGE_BYTES)    // 79872

__global__ void __launch_bounds__(256, 2) logits_kernel(const float* __restrict__ qry,
                                                        float* __restrict__ out) {
    extern __shared__ __align__(16) char smem[];
    const uint32_t sbase = (uint32_t)__cvta_generic_to_shared(smem);
    const int tid  = threadIdx.x;
    const int lane = tid & 31;
    const int wid  = tid >> 5;
    const int mt   = wid & 3;           // m16 tile 0..3
    const int nh   = wid >> 2;          // n32 half 0..1
    const int g    = lane >> 2;
    const int t    = lane & 3;
    const size_t rowBase = (size_t)blockIdx.x * 64;

    float acc[4][4];
    #pragma unroll
    for (int j = 0; j < 4; ++j)
        #pragma unroll
        for (int c = 0; c < 4; ++c) acc[j][c] = 0.f;

    // ---- stage K-tile tt into ring slot (tt%3) ----
    auto stage = [&](int tt) {
        const int k0 = tt * KT;
        const uint32_t sB = sbase + (uint32_t)(tt % 3) * STAGE_BYTES;
        #pragma unroll
        for (int jj = 0; jj < 4; ++jj) {
            const int c  = tid + jj * 256;   // 0..1023
            const int m  = c >> 4;           // row 0..63
            const int cw = c & 15;           // 16B chunk 0..15
            cp16(sB + (uint32_t)(m * (A_PITCH * 4) + cw * 16),
                 qry + (rowBase + m) * D_DIM + k0 + cw * 4);
        }
        const char* bsrc = (const char*)g_Ph + (size_t)tt * B_BYTES;
        #pragma unroll
        for (int jj = 0; jj < 2; ++jj) {
            const int c = tid + jj * 256;    // 0..511
            cp16(sB + (uint32_t)A_BYTES + (uint32_t)c * 16, bsrc + c * 16);
        }
        CP_COMMIT();
    };

    // ---- compute on ring slot of tile tt ----
    auto compute = [&](int tt) {
        const char* stg = smem + (size_t)(tt % 3) * STAGE_BYTES;
        const float* sA = (const float*)stg;
        const uint32_t* sBh = (const uint32_t*)(stg + A_BYTES);
        #pragma unroll
        for (int s = 0; s < 4; ++s) {        // k16-steps
            uint32_t bf[4][2];
            #pragma unroll
            for (int j = 0; j < 4; ++j) {
                const ull v = *(const ull*)(sBh + ((s * 8 + nh * 4 + j) * 32 + lane) * 2);
                bf[j][0] = (uint32_t)v;
                bf[j][1] = (uint32_t)(v >> 32);
            }
            const float* rg = sA + (mt * 16 + g) * A_PITCH + s * 16;
            const float* rh = rg + 8 * A_PITCH;
            const float2 p0 = *(const float2*)(rg + 2 * t);
            const float2 p1 = *(const float2*)(rg + 2 * t + 8);
            const float2 q0 = *(const float2*)(rh + 2 * t);
            const float2 q1 = *(const float2*)(rh + 2 * t + 8);
            uint32_t af[4];
            af[0] = f16x2_from(p0.x, p0.y);
            af[1] = f16x2_from(q0.x, q0.y);
            af[2] = f16x2_from(p1.x, p1.y);
            af[3] = f16x2_from(q1.x, q1.y);
            #pragma unroll
            for (int j = 0; j < 4; ++j)
                mma_f16(acc[j], af, bf[j][0], bf[j][1]);
        }
    };

    stage(0); stage(1);
    for (int tt = 0; tt < NT; ++tt) {
        if (tt + 2 < NT)      { stage(tt + 2); CP_WAIT(2); }
        else if (tt + 1 < NT) { CP_WAIT(1); }
        else                  { CP_WAIT(0); }
        __syncthreads();
        compute(tt);
        __syncthreads();
    }

    // ---- epilogue: scale x10, float2 stores ----
    const size_t r0 = rowBase + mt * 16 + g;
    #pragma unroll
    for (int j = 0; j < 4; ++j) {
        const int c0 = nh * 32 + j * 8 + t * 2;
        *(float2*)(out + r0 * 64 + c0) =
            make_float2(acc[j][0] * 10.f, acc[j][1] * 10.f);
        *(float2*)(out + (r0 + 8) * 64 + c0) =
            make_float2(acc[j][2] * 10.f, acc[j][3] * 10.f);
    }
}

// ======================================================================
extern "C" void kernel_launch(void* const* d_in, const int* in_sizes, int n_in,
                              void* d_out, int out_size) {
    const float* emb = (const float*)d_in[0];
    float* out = (float*)d_out;

    cudaFuncSetAttribute(logits_kernel,
                         cudaFuncAttributeMaxDynamicSharedMemorySize, SMEM_TOTAL);

    proto_mean<<<dim3(10, 64), 128>>>(emb);
    proto_w<<<dim3(8, 64), 256>>>(emb);
    proto_pd<<<N_CLS, 640>>>(emb);

    const float* qry = emb + (size_t)SUP_ROWS * D_DIM;
    logits_kernel<<<NQ / 64, 256, SMEM_TOTAL>>>(qry, out);
}

// round 9
// speedup vs baseline: 1.0765x; 1.0765x over previous
#include <cuda_runtime.h>
#include <cstdint>

// Problem constants
#define N_CLS 64
#define K_SHOT 64
#define D_DIM 640
#define Q_PER 2048
#define NQ (N_CLS * Q_PER)        // 131072 query rows
#define SUP_ROWS (N_CLS * K_SHOT) // 4096 support rows

typedef unsigned long long ull;

// Staging buffers
__device__ __align__(16) float g_pu2[2][N_CLS * D_DIM]; // partial sums (k-halves)

// Prototypes pre-packed as fp16x2 in mma.m16n8k16 B-fragment order:
//   g_Ph[((s*8 + j)*32 + l)*2 + r] = {f16(P[n][k_e0]), f16(P[n][k_e1])},
//   k = 16s + 2t + e + 8r (t = l&3), n = 8j + (l>>2),  s = 0..39.
__device__ __align__(16) uint32_t g_Ph[40 * 8 * 32 * 2];   // 80 KB

// ---------------- helpers ----------------
__device__ __forceinline__ uint32_t f16x2_from(float lo, float hi) {
    uint32_t r;
    asm("cvt.rn.f16x2.f32 %0, %1, %2;" : "=r"(r) : "f"(hi), "f"(lo));
    return r;
}
__device__ __forceinline__ void cp16(uint32_t dst, const void* src) {
    asm volatile("cp.async.cg.shared.global [%0], [%1], 16;" :: "r"(dst), "l"(src));
}
#define CP_COMMIT() asm volatile("cp.async.commit_group;" ::: "memory")
#define CP_WAIT(n)  asm volatile("cp.async.wait_group %0;" :: "n"(n) : "memory")

__device__ __forceinline__ void mma_f16(float* d, const uint32_t* a, uint32_t b0, uint32_t b1) {
    asm volatile(
        "mma.sync.aligned.m16n8k16.row.col.f32.f16.f16.f32 "
        "{%0,%1,%2,%3}, {%4,%5,%6,%7}, {%8,%9}, {%0,%1,%2,%3};"
        : "+f"(d[0]), "+f"(d[1]), "+f"(d[2]), "+f"(d[3])
        : "r"(a[0]), "r"(a[1]), "r"(a[2]), "r"(a[3]), "r"(b0), "r"(b1));
}

// ======================================================================
// Kernel 1a: proto_unnorm partial sums, K split in halves.
// grid (10, 64): bx%5 = d-chunk, bx/5 = k-half. 640 CTAs.
// ======================================================================
__global__ void __launch_bounds__(128) proto_mean(const float* __restrict__ emb) {
    const int i  = blockIdx.y;
    const int h  = blockIdx.x / 5;
    const int d  = (blockIdx.x % 5) * 128 + threadIdx.x;
    const float* base = emb + (size_t)(h * 32 * N_CLS + i) * D_DIM + d;
    float s = 0.f;
    #pragma unroll 32
    for (int k = 0; k < 32; ++k)
        s += base[(size_t)k * (N_CLS * D_DIM)];
    g_pu2[h][i * D_DIM + d] = s;
}

// ======================================================================
// Kernel 1b: fused cosine weights + weighted prototype + norm + scatter.
// grid (64), 640 threads. Support rows are L2-hot after proto_mean.
// ======================================================================
__global__ void __launch_bounds__(640) proto_wpd(const float* __restrict__ emb) {
    const int i    = blockIdx.x;
    const int tid  = threadIdx.x;   // doubles as dimension d
    const int lane = tid & 31;
    const int wid  = tid >> 5;      // 0..19

    __shared__ float s_pu[D_DIM];
    __shared__ float s_dis[64];
    __shared__ float s_red[20];
    __shared__ float s_pn, s_isum, s_inorm;

    // ---- assemble proto_unnorm + its norm ----
    float pn2 = 0.f;
    {
        const float s = (g_pu2[0][i * D_DIM + tid] + g_pu2[1][i * D_DIM + tid]) * (1.0f / 64.0f);
        s_pu[tid] = s;
        pn2 = s * s;
    }
    #pragma unroll
    for (int o = 16; o; o >>= 1) pn2 += __shfl_xor_sync(0xffffffffu, pn2, o);
    if (lane == 0) s_red[wid] = pn2;
    __syncthreads();
    if (tid == 0) {
        float t = 0.f;
        #pragma unroll
        for (int w = 0; w < 20; ++w) t += s_red[w];
        s_pn = fmaxf(sqrtf(t), 1e-8f);
    }
    __syncthreads();
    const float p_norm = s_pn;

    // ---- cosine weights: 20 warps cover 64 rows (strided) ----
    const float* blk = emb + (size_t)i * 64 * D_DIM;
    for (int j = wid; j < 64; j += 20) {
        const float* row = blk + (size_t)j * D_DIM;
        float dot = 0.f, s2 = 0.f;
        #pragma unroll 5
        for (int d = lane; d < D_DIM; d += 32) {
            float a = row[d];
            dot += a * s_pu[d];
            s2  += a * a;
        }
        #pragma unroll
        for (int o = 16; o; o >>= 1) {
            dot += __shfl_xor_sync(0xffffffffu, dot, o);
            s2  += __shfl_xor_sync(0xffffffffu, s2, o);
        }
        if (lane == 0) {
            float sn = fmaxf(sqrtf(s2), 1e-8f);
            s_dis[j] = expf(dot / (p_norm * sn));
        }
    }
    __syncthreads();

    // ---- softmax denominator ----
    if (tid < 32) {
        float v = s_dis[tid] + s_dis[tid + 32];
        #pragma unroll
        for (int o = 16; o; o >>= 1) v += __shfl_xor_sync(0xffffffffu, v, o);
        if (tid == 0) s_isum = 1.0f / v;
    }
    __syncthreads();
    const float inv_sum = s_isum;

    // ---- weighted prototype (thread = dimension) ----
    const float* col = blk + tid;
    float pd = 0.f;
    #pragma unroll 8
    for (int j = 0; j < 64; ++j)
        pd += (s_dis[j] * inv_sum) * col[(size_t)j * D_DIM];

    float q2 = pd * pd;
    #pragma unroll
    for (int o = 16; o; o >>= 1) q2 += __shfl_xor_sync(0xffffffffu, q2, o);
    __syncthreads();              // protect s_red reuse
    if (lane == 0) s_red[wid] = q2;
    __syncthreads();
    if (tid == 0) {
        float t = 0.f;
        #pragma unroll
        for (int w = 0; w < 20; ++w) t += s_red[w];
        s_inorm = 1.0f / fmaxf(sqrtf(t), 1e-12f);
    }
    __syncthreads();

    // reuse s_pu to hold the normalized prototype
    s_pu[tid] = pd * s_inorm;
    __syncthreads();

    // ---- pack pairs into fp16 B-fragment layout ----
    if (tid < 320) {
        const int s  = tid >> 3;
        const int t4 = (tid & 7) >> 1;
        const int r  = tid & 1;
        const int k0 = 16 * s + 2 * t4 + 8 * r;
        const int ln = 4 * (i & 7) + t4;
        const int idx = ((s * 8 + (i >> 3)) * 32 + ln) * 2 + r;
        g_Ph[idx] = f16x2_from(s_pu[k0], s_pu[k0 + 1]);
    }
}

// ======================================================================
// Kernel 2: logits = query @ P^T * 10 via mma.sync m16n8k16 fp16.
//   (exact R7 configuration — measured 67us, DRAM 65.8%)
//   Block 256 thr (8 warps), M-tile 128 (warp = one m16 tile), N=64,
//   KT=64 (4 k16-steps), double-buffered cp.async.
// ======================================================================
#define KT 64
#define NT (D_DIM / KT)                 // 10 K-tiles
#define A_PITCH 72
#define A_BYTES (128 * A_PITCH * 4)     // 36864
#define B_BYTES (4 * 8 * 32 * 2 * 4)    // 8192 (4 k16-steps)
#define STAGE_BYTES (A_BYTES + B_BYTES) // 45056
#define SMEM_TOTAL (2 * STAGE_BYTES)    // 90112

__global__ void __launch_bounds__(256, 2) logits_kernel(const float* __restrict__ qry,
                                                        float* __restrict__ out) {
    extern __shared__ __align__(16) char smem[];
    const uint32_t sbase = (uint32_t)__cvta_generic_to_shared(smem);
    const int tid  = threadIdx.x;
    const int lane = tid & 31;
    const int wid  = tid >> 5;          // warp = m16 tile 0..7
    const int g    = lane >> 2;
    const int t    = lane & 3;
    const size_t rowBase = (size_t)blockIdx.x * 128;

    float acc[8][4];
    #pragma unroll
    for (int j = 0; j < 8; ++j)
        #pragma unroll
        for (int c = 0; c < 4; ++c) acc[j][c] = 0.f;

    auto stage = [&](int tt) {
        const int k0 = tt * KT;
        const uint32_t sB = sbase + (uint32_t)(tt & 1) * STAGE_BYTES;
        #pragma unroll
        for (int jj = 0; jj < 8; ++jj) {
            const int c  = tid + jj * 256;   // 0..2047
            const int m  = c >> 4;           // row 0..127
            const int cw = c & 15;           // 16B chunk 0..15
            cp16(sB + (uint32_t)(m * (A_PITCH * 4) + cw * 16),
                 qry + (rowBase + m) * D_DIM + k0 + cw * 4);
        }
        const char* bsrc = (const char*)g_Ph + (size_t)tt * B_BYTES;
        #pragma unroll
        for (int jj = 0; jj < 2; ++jj) {
            const int c = tid + jj * 256;    // 0..511
            cp16(sB + (uint32_t)A_BYTES + (uint32_t)c * 16, bsrc + c * 16);
        }
        CP_COMMIT();
    };

    auto compute = [&](int tt) {
        const char* stg = smem + (size_t)(tt & 1) * STAGE_BYTES;
        const float* sA = (const float*)stg;
        const uint32_t* sBh = (const uint32_t*)(stg + A_BYTES);
        #pragma unroll
        for (int s = 0; s < 4; ++s) {        // k16-steps
            uint32_t bf[8][2];
            #pragma unroll
            for (int j = 0; j < 8; ++j) {
                const ull v = *(const ull*)(sBh + ((s * 8 + j) * 32 + lane) * 2);
                bf[j][0] = (uint32_t)v;
                bf[j][1] = (uint32_t)(v >> 32);
            }
            const float* rg = sA + (wid * 16 + g) * A_PITCH + s * 16;
            const float* rh = rg + 8 * A_PITCH;
            const float2 p0 = *(const float2*)(rg + 2 * t);
            const float2 p1 = *(const float2*)(rg + 2 * t + 8);
            const float2 q0 = *(const float2*)(rh + 2 * t);
            const float2 q1 = *(const float2*)(rh + 2 * t + 8);
            uint32_t af[4];
            af[0] = f16x2_from(p0.x, p0.y);
            af[1] = f16x2_from(q0.x, q0.y);
            af[2] = f16x2_from(p1.x, p1.y);
            af[3] = f16x2_from(q1.x, q1.y);
            #pragma unroll
            for (int j = 0; j < 8; ++j)
                mma_f16(acc[j], af, bf[j][0], bf[j][1]);
        }
    };

    stage(0);
    for (int tt = 0; tt < NT; ++tt) {
        if (tt + 1 < NT) { stage(tt + 1); CP_WAIT(1); }
        else             { CP_WAIT(0); }
        __syncthreads();
        compute(tt);
        __syncthreads();
    }

    const size_t r0 = rowBase + wid * 16 + g;
    #pragma unroll
    for (int j = 0; j < 8; ++j) {
        const int c0 = j * 8 + t * 2;
        *(float2*)(out + r0 * 64 + c0) =
            make_float2(acc[j][0] * 10.f, acc[j][1] * 10.f);
        *(float2*)(out + (r0 + 8) * 64 + c0) =
            make_float2(acc[j][2] * 10.f, acc[j][3] * 10.f);
    }
}

// ======================================================================
extern "C" void kernel_launch(void* const* d_in, const int* in_sizes, int n_in,
                              void* d_out, int out_size) {
    const float* emb = (const float*)d_in[0];
    float* out = (float*)d_out;

    cudaFuncSetAttribute(logits_kernel,
                         cudaFuncAttributeMaxDynamicSharedMemorySize, SMEM_TOTAL);

    proto_mean<<<dim3(10, 64), 128>>>(emb);
    proto_wpd<<<N_CLS, 640>>>(emb);

    const float* qry = emb + (size_t)SUP_ROWS * D_DIM;
    logits_kernel<<<NQ / 128, 256, SMEM_TOTAL>>>(qry, out);
}